// round 1
// baseline (speedup 1.0000x reference)
#include <cuda_runtime.h>

#define B_SZ 512
#define D_SZ 1024
#define P_SZ 16
#define N_SZ 128
#define ALPHA_F 0.8f
#define NROWS (1 + P_SZ + N_SZ)   // 145: row 0 = tgt, 1..16 = rel, 17..144 = irr

__device__ float g_partials[B_SZ];

__global__ void __launch_bounds__(256, 4)
contrastive_loss_kernel(const float* __restrict__ src,
                        const float* __restrict__ tgt,
                        const float* __restrict__ rel,
                        const float* __restrict__ irr)
{
    __shared__ float s_src[D_SZ];
    __shared__ float s_red[8];
    __shared__ float s_pos[8];
    __shared__ float s_neg[8];
    __shared__ float s_diag;
    __shared__ float s_inv;

    const int b    = blockIdx.x;
    const int tid  = threadIdx.x;
    const int wid  = tid >> 5;
    const int lane = tid & 31;

    // ---- load src row into shared; accumulate its sum of squares ----
    const float4* srcv = reinterpret_cast<const float4*>(src + (size_t)b * D_SZ);
    float ss = 0.f;
    #pragma unroll
    for (int i = 0; i < D_SZ / 4 / 256; i++) {
        int idx = i * 256 + tid;
        float4 v = srcv[idx];
        reinterpret_cast<float4*>(s_src)[idx] = v;
        ss += v.x * v.x + v.y * v.y + v.z * v.z + v.w * v.w;
    }
    #pragma unroll
    for (int o = 16; o > 0; o >>= 1) ss += __shfl_xor_sync(0xFFFFFFFFu, ss, o);
    if (lane == 0) s_red[wid] = ss;
    __syncthreads();
    if (tid == 0) {
        float t = 0.f;
        #pragma unroll
        for (int i = 0; i < 8; i++) t += s_red[i];
        // 1 / max(||src||, 1e-12)  ==  rsqrt(max(ss, 1e-24))
        s_inv = rsqrtf(fmaxf(t, 1e-24f));
    }
    __syncthreads();
    const float inv_src = s_inv;

    // ---- stream passage rows: dot against s_src + row sumsq in one pass ----
    float pos_acc = 0.f, neg_acc = 0.f;

    for (int r = wid; r < NROWS; r += 8) {
        const float* row;
        if (r == 0)
            row = tgt + (size_t)b * D_SZ;
        else if (r <= P_SZ)
            row = rel + ((size_t)b * P_SZ + (r - 1)) * D_SZ;
        else
            row = irr + ((size_t)b * N_SZ + (r - 1 - P_SZ)) * D_SZ;

        const float4* rv = reinterpret_cast<const float4*>(row);
        float dot = 0.f, rss = 0.f;
        #pragma unroll
        for (int j = 0; j < D_SZ / 4 / 32; j++) {   // 8 iterations, 8 LDG.128 in flight
            int idx = j * 32 + lane;
            float4 v = rv[idx];
            float4 s = reinterpret_cast<const float4*>(s_src)[idx];
            dot += v.x * s.x + v.y * s.y + v.z * s.z + v.w * s.w;
            rss += v.x * v.x + v.y * v.y + v.z * v.z + v.w * v.w;
        }
        #pragma unroll
        for (int o = 16; o > 0; o >>= 1) {
            dot += __shfl_xor_sync(0xFFFFFFFFu, dot, o);
            rss += __shfl_xor_sync(0xFFFFFFFFu, rss, o);
        }
        if (lane == 0) {
            float c = dot * inv_src * rsqrtf(fmaxf(rss, 1e-24f));
            if (r == 0)            s_diag = c;
            else if (r <= P_SZ)    pos_acc += expf(c);
            else                   neg_acc += expf(c);
        }
    }

    if (lane == 0) { s_pos[wid] = pos_acc; s_neg[wid] = neg_acc; }
    __syncthreads();

    if (tid == 0) {
        float ps = 0.f, ns = 0.f;
        #pragma unroll
        for (int i = 0; i < 8; i++) { ps += s_pos[i]; ns += s_neg[i]; }
        float pos_score = 1.f + ps;
        float lp = logf(pos_score);
        float ln = logf(pos_score + ns);
        float loss_b = -(ALPHA_F * s_diag + (1.f - ALPHA_F) * (lp - ln));
        g_partials[b] = loss_b;
    }
}

__global__ void __launch_bounds__(256)
reduce_kernel(float* __restrict__ out)
{
    __shared__ float s[256];
    int tid = threadIdx.x;
    s[tid] = g_partials[tid] + g_partials[tid + 256];
    __syncthreads();
    #pragma unroll
    for (int o = 128; o > 0; o >>= 1) {
        if (tid < o) s[tid] += s[tid + o];
        __syncthreads();
    }
    if (tid == 0) out[0] = s[0] * (1.0f / (float)B_SZ);
}

extern "C" void kernel_launch(void* const* d_in, const int* in_sizes, int n_in,
                              void* d_out, int out_size)
{
    const float* src = (const float*)d_in[0];   // [B, D]
    const float* tgt = (const float*)d_in[1];   // [B, D]
    const float* rel = (const float*)d_in[2];   // [B, P, D]
    const float* irr = (const float*)d_in[3];   // [B, N, D]
    float* out = (float*)d_out;

    contrastive_loss_kernel<<<B_SZ, 256>>>(src, tgt, rel, irr);
    reduce_kernel<<<1, 256>>>(out);
}